// round 2
// baseline (speedup 1.0000x reference)
#include <cuda_runtime.h>
#include <cuda_bf16.h>

// MarginRankingLoss: x[V=4096, C=128, T=128] fp32, target[V,C] int64 -> scalar.
// loss = ( sum_{v,c,t} max(0, x - x[target] + 0.5) - 0.5*V*C ) / (V*C*(T-1))
// (the target position always contributes exactly 0.5, subtracted analytically)
//
// Single-launch threadfence reduction: each block writes a partial, the last
// block to arrive reduces all partials, writes out[0], and resets the counter
// (so state returns to initial -> deterministic across CUDA-graph replays).

#define NROWS (4096 * 128)   // V*C
#define TDIM 128
#define NBLOCKS 2048
#define NTHREADS 256

__device__ float        g_partials[NBLOCKS];
__device__ unsigned int g_count;   // zero-initialized; restored to 0 each call

__global__ __launch_bounds__(NTHREADS) void mrl_fused_kernel(
    const float4* __restrict__ x,          // [NROWS * 32] float4 view
    const long long* __restrict__ target,  // [NROWS]
    float* __restrict__ out)
{
    const int lane  = threadIdx.x & 31;
    const int warp  = (blockIdx.x * NTHREADS + threadIdx.x) >> 5;
    const int nwarp = (NBLOCKS * NTHREADS) >> 5;

    float acc = 0.0f;

    for (int row = warp; row < NROWS; row += nwarp) {
        const float4 v = x[row * 32 + lane];
        const int t = (int)target[row];

        // extract x[row][t]: lane t>>2 holds it in element t&3
        float p = (t & 2) ? ((t & 1) ? v.w : v.z)
                          : ((t & 1) ? v.y : v.x);
        const float pos = __shfl_sync(0xffffffffu, p, t >> 2);

        const float b = 0.5f - pos;
        acc += fmaxf(v.x + b, 0.0f) + fmaxf(v.y + b, 0.0f)
             + fmaxf(v.z + b, 0.0f) + fmaxf(v.w + b, 0.0f);
    }

    // warp reduce
    #pragma unroll
    for (int o = 16; o; o >>= 1)
        acc += __shfl_xor_sync(0xffffffffu, acc, o);

    __shared__ float smem[NTHREADS / 32];
    __shared__ bool  s_last;
    if (lane == 0) smem[threadIdx.x >> 5] = acc;
    __syncthreads();

    if (threadIdx.x == 0) {
        float bsum = 0.0f;
        #pragma unroll
        for (int w = 0; w < NTHREADS / 32; w++) bsum += smem[w];
        g_partials[blockIdx.x] = bsum;
        __threadfence();                       // make partial visible before count
        unsigned int prev = atomicAdd(&g_count, 1u);
        s_last = (prev == NBLOCKS - 1);
    }
    __syncthreads();

    if (s_last) {
        // last block: reduce all 2048 partials in double
        const volatile float* vp = g_partials;
        double d = 0.0;
        for (int i = threadIdx.x; i < NBLOCKS; i += NTHREADS)
            d += (double)vp[i];

        // warp reduce in double
        #pragma unroll
        for (int o = 16; o; o >>= 1)
            d += __shfl_xor_sync(0xffffffffu, d, o);

        __shared__ double dsm[NTHREADS / 32];
        if (lane == 0) dsm[threadIdx.x >> 5] = d;
        __syncthreads();

        if (threadIdx.x == 0) {
            double tot = 0.0;
            #pragma unroll
            for (int w = 0; w < NTHREADS / 32; w++) tot += dsm[w];
            const double corrected = tot - 0.5 * (double)NROWS;
            out[0] = (float)(corrected / ((double)NROWS * (double)(TDIM - 1)));
            g_count = 0;                       // restore state for next replay
        }
    }
}

extern "C" void kernel_launch(void* const* d_in, const int* in_sizes, int n_in,
                              void* d_out, int out_size) {
    const float4*    x   = (const float4*)d_in[0];
    const long long* tgt = (const long long*)d_in[1];
    float*           out = (float*)d_out;

    mrl_fused_kernel<<<NBLOCKS, NTHREADS>>>(x, tgt, out);
}

// round 4
// speedup vs baseline: 1.1413x; 1.1413x over previous
#include <cuda_runtime.h>
#include <cuda_bf16.h>

// MarginRankingLoss: x[V=4096, C=128, T=128] fp32, target[V,C] int64 -> scalar.
// loss = ( sum_{v,c,t} max(0, x - x[target] + 0.5) - 0.5*V*C ) / (V*C*(T-1))
// (the target position always contributes exactly 0.5, subtracted analytically)
//
// 3-kernel graph (zero -> main -> finalize); tiny kernels cost ~1us each in a
// captured graph (measured R1 vs R2: fusion with a last-block tail was SLOWER).
// Main loop: blocked rows per warp (32 rows/warp, FULL coverage: 16384 warps
// x 32 = 524288 rows), coalesced target prefetch, MLP-4 unroll, streaming loads.

#define NROWS (4096 * 128)   // V*C = 524288
#define TDIM 128
#define NBLOCKS 2048
#define NTHREADS 256
#define ROWS_PER_WARP 32     // NROWS / (NBLOCKS * NTHREADS / 32) = 524288/16384

__device__ double g_mrl_sum;

__global__ void mrl_zero_kernel() {
    g_mrl_sum = 0.0;
}

__global__ __launch_bounds__(NTHREADS) void mrl_main_kernel(
    const float4* __restrict__ x,          // [NROWS * 32] float4 view
    const long long* __restrict__ target)  // [NROWS]
{
    const int lane = threadIdx.x & 31;
    const int warp = (blockIdx.x * NTHREADS + threadIdx.x) >> 5;
    const int base = warp * ROWS_PER_WARP;

    // One coalesced 256B load fetches this warp's 32 int64 targets.
    const int tt = (int)target[base + lane];

    float acc = 0.0f;

    #pragma unroll 4
    for (int i = 0; i < ROWS_PER_WARP; i++) {
        const float4 v = __ldcs(&x[(base + i) * 32 + lane]);
        const int t = __shfl_sync(0xffffffffu, tt, i);

        // extract x[row][t]: lane t>>2 holds it in element t&3
        float p = (t & 2) ? ((t & 1) ? v.w : v.z)
                          : ((t & 1) ? v.y : v.x);
        const float pos = __shfl_sync(0xffffffffu, p, t >> 2);

        const float b = 0.5f - pos;
        acc += fmaxf(v.x + b, 0.0f) + fmaxf(v.y + b, 0.0f)
             + fmaxf(v.z + b, 0.0f) + fmaxf(v.w + b, 0.0f);
    }

    // warp reduce
    #pragma unroll
    for (int o = 16; o; o >>= 1)
        acc += __shfl_xor_sync(0xffffffffu, acc, o);

    __shared__ float smem[NTHREADS / 32];
    if (lane == 0) smem[threadIdx.x >> 5] = acc;
    __syncthreads();

    if (threadIdx.x == 0) {
        float bsum = 0.0f;
        #pragma unroll
        for (int w = 0; w < NTHREADS / 32; w++) bsum += smem[w];
        atomicAdd(&g_mrl_sum, (double)bsum);
    }
}

__global__ void mrl_finalize_kernel(float* __restrict__ out) {
    // subtract the target-position hinge (exactly 0.5 per row), then mean
    const double corrected = g_mrl_sum - 0.5 * (double)NROWS;
    out[0] = (float)(corrected / ((double)NROWS * (double)(TDIM - 1)));
}

extern "C" void kernel_launch(void* const* d_in, const int* in_sizes, int n_in,
                              void* d_out, int out_size) {
    const float4*    x   = (const float4*)d_in[0];
    const long long* tgt = (const long long*)d_in[1];
    float*           out = (float*)d_out;

    mrl_zero_kernel<<<1, 1>>>();
    mrl_main_kernel<<<NBLOCKS, NTHREADS>>>(x, tgt);
    mrl_finalize_kernel<<<1, 1>>>(out);
}